// round 4
// baseline (speedup 1.0000x reference)
#include <cuda_runtime.h>
#include <cstdint>

#define BATCH   128
#define INPUTS  65536
#define OUTPUTS 65536
#define TOPK    32

// 32 MB transposed activation scratch: xT[i][b] = x[b][i]
__device__ float g_xT[(size_t)INPUTS * BATCH];

// ---------------------------------------------------------------------------
// Kernel 1: tiled transpose x (B, INPUTS) -> g_xT (INPUTS, B)
// ---------------------------------------------------------------------------
__global__ void transpose_kernel(const float* __restrict__ x) {
    __shared__ float tile[32][33];
    const int i0 = blockIdx.x * 32;
    const int b0 = blockIdx.y * 32;
    const int tx = threadIdx.x;
    const int ty = threadIdx.y;  // block (32, 8)

#pragma unroll
    for (int r = ty; r < 32; r += 8)
        tile[r][tx] = x[(size_t)(b0 + r) * INPUTS + (i0 + tx)];
    __syncthreads();
#pragma unroll
    for (int r = ty; r < 32; r += 8)
        g_xT[(size_t)(i0 + r) * BATCH + (b0 + tx)] = tile[tx][r];
}

// ---------------------------------------------------------------------------
// Kernel 2: per-output softmax + weighted gather from L2-resident xT.
// Block = 256 threads = 8 warps. Block handles 32 output columns (4 per warp).
// ---------------------------------------------------------------------------
__global__ __launch_bounds__(256) void gather_kernel(
    const float* __restrict__ top_c,
    const void*  __restrict__ idx_raw,
    float*       __restrict__ out) {

    __shared__ __align__(16) float sm_out[32][BATCH + 4];  // +4 keeps 16B row alignment
    __shared__ float sm_w[8][TOPK];
    __shared__ int   sm_r[8][TOPK];

    // int64-vs-int32 index dtype detection (uniform across the grid):
    // if indices are int64 (values < 65536), the high words are all zero.
    const unsigned* pu = (const unsigned*)idx_raw;
    const bool is64 = ((pu[1] | pu[3] | pu[5] | pu[7]) == 0u);

    const int warp  = threadIdx.x >> 5;
    const int lane  = threadIdx.x & 31;
    const int o_blk = blockIdx.x * 32;

#pragma unroll
    for (int j = 0; j < 4; j++) {
        const int ol = warp * 4 + j;
        const int o  = o_blk + ol;

        // lane index == k
        float c = top_c[(size_t)lane * OUTPUTS + o];
        int row;
        if (is64) row = (int)((const long long*)idx_raw)[(size_t)lane * OUTPUTS + o];
        else      row =       ((const int*)      idx_raw)[(size_t)lane * OUTPUTS + o];

        // softmax over k (warp reduction); C_SPARSITY == 1.0
        float m = c;
#pragma unroll
        for (int d = 16; d; d >>= 1) m = fmaxf(m, __shfl_xor_sync(0xffffffffu, m, d));
        float e = __expf(c - m);
        float s = e;
#pragma unroll
        for (int d = 16; d; d >>= 1) s += __shfl_xor_sync(0xffffffffu, s, d);
        const float w = e / s;

        sm_w[warp][lane] = w;
        sm_r[warp][lane] = row;
        __syncwarp();

        // 32 independent 512B row gathers (warp-wide float4), fp32 accumulate.
        float4 acc = make_float4(0.f, 0.f, 0.f, 0.f);
#pragma unroll
        for (int k = 0; k < TOPK; k++) {
            const float wk = sm_w[warp][k];
            const int   rk = sm_r[warp][k];
            const float4 v = *((const float4*)(g_xT + (size_t)rk * BATCH) + lane);
            acc.x += wk * v.x;
            acc.y += wk * v.y;
            acc.z += wk * v.z;
            acc.w += wk * v.w;
        }
        *((float4*)&sm_out[ol][lane * 4]) = acc;
        __syncwarp();
    }
    __syncthreads();

    // Coalesced output: each warp writes one batch-row span of 32 consecutive
    // output columns (128B contiguous stores).
    for (int t = threadIdx.x; t < 32 * BATCH; t += 256) {
        const int b  = t >> 5;
        const int ol = t & 31;
        out[(size_t)b * OUTPUTS + (o_blk + ol)] = sm_out[ol][b];
    }
}

// ---------------------------------------------------------------------------
extern "C" void kernel_launch(void* const* d_in, const int* in_sizes, int n_in,
                              void* d_out, int out_size) {
    const float* x     = (const float*)d_in[0];
    const float* top_c = (const float*)d_in[1];
    const void*  idx   = d_in[2];
    float*       out   = (float*)d_out;

    dim3 tb(32, 8);
    dim3 tg(INPUTS / 32, BATCH / 32);
    transpose_kernel<<<tg, tb>>>(x);

    gather_kernel<<<OUTPUTS / 32, 256>>>(top_c, idx, out);
}